// round 13
// baseline (speedup 1.0000x reference)
#include <cuda_runtime.h>
#include <cuda_fp16.h>
#include <cstdint>

#define GN 8192

// ---------------------------------------------------------------------------
// Device-global scratch (allocation-free per harness rules)
// ---------------------------------------------------------------------------
__device__ float g_dinv[GN];
__device__ __half g_adj_h[(size_t)GN * GN];           // fp16 adj, 128 MB
// double-buffered per layer (ping-pong): fp32 Zs + transposed fp16 plane [n][k]
__device__ float g_Zs[2][(size_t)GN * 128];
__device__ __half g_Bh[2][(size_t)128 * GN];

// ---------------------------------------------------------------------------
// PTX helpers (compute_103-safe: cp.async + ldmatrix + mma.sync only)
// ---------------------------------------------------------------------------
__device__ __forceinline__ uint32_t smem_u32(const void* p) {
    uint32_t a;
    asm("{ .reg .u64 t; cvta.to.shared.u64 t, %1; cvt.u32.u64 %0, t; }" : "=r"(a) : "l"(p));
    return a;
}
__device__ __forceinline__ void cp16(uint32_t dst, const void* src) {
    asm volatile("cp.async.cg.shared.global [%0], [%1], 16;" :: "r"(dst), "l"(src));
}
__device__ __forceinline__ void cp_commit() { asm volatile("cp.async.commit_group;" ::: "memory"); }
template<int N>
__device__ __forceinline__ void cp_wait() { asm volatile("cp.async.wait_group %0;" :: "n"(N) : "memory"); }

__device__ __forceinline__ void ldsm4(uint32_t* r, uint32_t addr) {
    asm volatile("ldmatrix.sync.aligned.m8n8.x4.shared.b16 {%0,%1,%2,%3}, [%4];"
                 : "=r"(r[0]), "=r"(r[1]), "=r"(r[2]), "=r"(r[3]) : "r"(addr));
}
__device__ __forceinline__ void mma_f16(float* d, const uint32_t* a, const uint32_t* b) {
    asm volatile("mma.sync.aligned.m16n8k16.row.col.f32.f16.f16.f32 "
                 "{%0,%1,%2,%3}, {%4,%5,%6,%7}, {%8,%9}, {%0,%1,%2,%3};"
                 : "+f"(d[0]), "+f"(d[1]), "+f"(d[2]), "+f"(d[3])
                 : "r"(a[0]), "r"(a[1]), "r"(a[2]), "r"(a[3]), "r"(b[0]), "r"(b[1]));
}

// ---------------------------------------------------------------------------
// Kernel 1: rowsum (fp32-exact) + fp32 -> fp16 convert of adj (fused one pass)
// ---------------------------------------------------------------------------
__global__ void __launch_bounds__(256) convert_rowsum(const float* __restrict__ adj) {
    int row = blockIdx.x;
    int tid = threadIdx.x;
    const float4* src = reinterpret_cast<const float4*>(adj + (size_t)row * GN);
    uint4* dst = reinterpret_cast<uint4*>(g_adj_h + (size_t)row * GN);
    float s = 0.f;
    #pragma unroll
    for (int i = tid; i < GN / 8; i += 256) {
        float4 v0 = src[2 * i];
        float4 v1 = src[2 * i + 1];
        s += ((v0.x + v0.y) + (v0.z + v0.w)) + ((v1.x + v1.y) + (v1.z + v1.w));
        __half2 p0 = __floats2half2_rn(v0.x, v0.y);
        __half2 p1 = __floats2half2_rn(v0.z, v0.w);
        __half2 p2 = __floats2half2_rn(v1.x, v1.y);
        __half2 p3 = __floats2half2_rn(v1.z, v1.w);
        uint4 u;
        u.x = *reinterpret_cast<uint32_t*>(&p0);
        u.y = *reinterpret_cast<uint32_t*>(&p1);
        u.z = *reinterpret_cast<uint32_t*>(&p2);
        u.w = *reinterpret_cast<uint32_t*>(&p3);
        dst[i] = u;
    }
    __shared__ float red[8];
    #pragma unroll
    for (int o = 16; o; o >>= 1) s += __shfl_down_sync(0xffffffffu, s, o);
    if ((tid & 31) == 0) red[tid >> 5] = s;
    __syncthreads();
    if (tid == 0) {
        float t = 0.f;
        #pragma unroll
        for (int w = 0; w < 8; w++) t += red[w];
        g_dinv[row] = rsqrtf(t + 1.0f);
    }
}

// ---------------------------------------------------------------------------
// Kernel 2 (layer 0 only): Zs = dinv ⊙ (x @ W0) -> buffer 0 (fp32 + fp16 plane)
// ---------------------------------------------------------------------------
template<int K, int NC>
__global__ void __launch_bounds__(256) feat_gemm(const float* __restrict__ Xin,
                                                 const float* __restrict__ W) {
    constexpr int CW = NC / 16;
    __shared__ float hs[64][K];
    __shared__ float ws[16][NC];
    int tid = threadIdx.x;
    int r0 = blockIdx.x * 64;
    int tx = tid & 15, ty = tid >> 4;

    {
        const float4* s4 = reinterpret_cast<const float4*>(Xin + (size_t)r0 * K);
        float4* d4 = reinterpret_cast<float4*>(&hs[0][0]);
        for (int i = tid; i < 64 * K / 4; i += 256) d4[i] = s4[i];
    }
    float acc[4][CW];
    #pragma unroll
    for (int r = 0; r < 4; r++)
        #pragma unroll
        for (int c = 0; c < CW; c++) acc[r][c] = 0.f;

    for (int kc = 0; kc < K / 16; kc++) {
        __syncthreads();
        {
            const float4* s4 = reinterpret_cast<const float4*>(W + kc * 16 * NC);
            float4* d4 = reinterpret_cast<float4*>(&ws[0][0]);
            for (int i = tid; i < 16 * NC / 4; i += 256) d4[i] = s4[i];
        }
        __syncthreads();
        #pragma unroll
        for (int k = 0; k < 16; k++) {
            float a0 = hs[ty * 4 + 0][kc * 16 + k];
            float a1 = hs[ty * 4 + 1][kc * 16 + k];
            float a2 = hs[ty * 4 + 2][kc * 16 + k];
            float a3 = hs[ty * 4 + 3][kc * 16 + k];
            #pragma unroll
            for (int c = 0; c < CW; c++) {
                float w = ws[k][c * 16 + tx];
                acc[0][c] = fmaf(a0, w, acc[0][c]);
                acc[1][c] = fmaf(a1, w, acc[1][c]);
                acc[2][c] = fmaf(a2, w, acc[2][c]);
                acc[3][c] = fmaf(a3, w, acc[3][c]);
            }
        }
    }
    #pragma unroll
    for (int r = 0; r < 4; r++) {
        int row = r0 + ty * 4 + r;
        float di = g_dinv[row];
        #pragma unroll
        for (int c = 0; c < CW; c++) {
            int col = c * 16 + tx;
            float z = di * acc[r][c];
            g_Zs[0][(size_t)row * NC + col] = z;
            g_Bh[0][(size_t)col * GN + row] = __float2half_rn(z);
        }
    }
}

// ---------------------------------------------------------------------------
// Kernel 3: single-pass fp16 HMMA SpMM + fused epilogue
//   h = [relu]( dinv[i]*( adj_h@Bh + Zs[i,:] ) + bias )
//   If NC>0: also computes next layer's Zs = dinv ⊙ (h @ W) in-kernel.
//   BM=64 (128 CTAs), 512 threads = 16 warps:
//     4 warp positions (2m x 2n), each a 32 x BN/2 tile;
//     4-way K-split across warp groups (wg = warp>>2), reduced via smem.
//   BK=64, 4-stage cp.async. smem rows 128B, swizzle chunk' = c ^ (row & 7).
// ---------------------------------------------------------------------------
template<int BN, int NC, int SRC, bool RELU>
__global__ void __launch_bounds__(512) spmm_hmma(const float* __restrict__ bias,
                                                 const float* __restrict__ Wn,
                                                 float* __restrict__ Out) {
    constexpr int BK = 64;
    constexpr int NT = GN / BK;               // 128 k-tiles
    constexpr int ASZ = 64 * BK * 2;          // 8 KB fp16 A plane
    constexpr int BSZ = BN * BK * 2;          // fp16 B plane
    constexpr int STAGE = ASZ + BSZ;
    constexpr int WN = BN / 2;                // warp-position n extent (64 or 32)
    constexpr int NF = WN / 8;                // n8 fragments (8 or 4)
    constexpr int QF = 2 * NF * 4;            // accum floats per thread (64 or 32)
    constexpr int EPIH = (NC > 0) ? (BN * 66 * 4 + BN * NC * 4) : 0;
    constexpr int MAINSZ = 4 * STAGE;
    constexpr int RBUF_OFF = (MAINSZ > EPIH) ? MAINSZ : EPIH;

    extern __shared__ char smem[];
    const uint32_t sb0 = smem_u32(smem);

    const int tid = threadIdx.x;
    const int lane = tid & 31;
    const int warp = tid >> 5;
    const int wg = warp >> 2;                 // k-split group 0..3
    const int wp = warp & 3;                  // warp position
    const int wm = wp >> 1;                   // 0..1 (32 rows each)
    const int wn = wp & 1;                    // 0..1
    const int m0 = blockIdx.x * 64;
    const int n0c = wn * WN;

    float acc[2][NF][4];
    #pragma unroll
    for (int mt = 0; mt < 2; mt++)
        #pragma unroll
        for (int nf = 0; nf < NF; nf++)
            #pragma unroll
            for (int q = 0; q < 4; q++) acc[mt][nf][q] = 0.f;

    auto issue = [&](int kt) {
        if (kt < NT) {
            const uint32_t sb = sb0 + (kt & 3) * STAGE;
            const int k0 = kt * BK;
            {   // A: 64 rows x 8 chunks = 512 -> 1 chunk/thread
                int row = tid >> 3, c = tid & 7;
                uint32_t so = row * 128 + ((c ^ (row & 7)) << 4);
                cp16(sb + so, g_adj_h + (size_t)(m0 + row) * GN + k0 + c * 8);
            }
            #pragma unroll
            for (int j = 0; j < BN / 64; j++) {  // B: BN rows x 8 chunks
                int idx = tid + j * 512;
                int row = idx >> 3, c = idx & 7;
                uint32_t so = row * 128 + ((c ^ (row & 7)) << 4);
                cp16(sb + ASZ + so, g_Bh[SRC] + (size_t)row * GN + k0 + c * 8);
            }
        }
        cp_commit();
    };

    issue(0); issue(1); issue(2);

    #pragma unroll 1
    for (int kt = 0; kt < NT; kt++) {
        cp_wait<2>();
        __syncthreads();
        issue(kt + 3);            // refills slot (kt-1)&3, safe post-sync

        const uint32_t sb = sb0 + (kt & 3) * STAGE;
        const int kc = wg * 2;    // this group's k16 step (16B chunk base)
        uint32_t af[2][4];
        #pragma unroll
        for (int mt = 0; mt < 2; mt++) {
            int row = wm * 32 + mt * 16 + (lane & 15);
            int ch = (kc + (lane >> 4)) ^ (row & 7);
            ldsm4(af[mt], sb + row * 128 + ch * 16);
        }
        uint32_t bf[NF][2];
        #pragma unroll
        for (int bt = 0; bt < NF / 2; bt++) {
            int row = n0c + bt * 16 + (lane & 7) + ((lane >> 4) << 3);
            int ch = (kc + ((lane >> 3) & 1)) ^ (row & 7);
            uint32_t t[4];
            ldsm4(t, sb + ASZ + row * 128 + ch * 16);
            bf[2 * bt][0] = t[0]; bf[2 * bt][1] = t[1];
            bf[2 * bt + 1][0] = t[2]; bf[2 * bt + 1][1] = t[3];
        }
        #pragma unroll
        for (int mt = 0; mt < 2; mt++)
            #pragma unroll
            for (int nf = 0; nf < NF; nf++)
                mma_f16(acc[mt][nf], af[mt], bf[nf]);
    }

    // ---- K-split reduction: wg1..3 dump accumulators, wg0 adds ----
    float* rbuf = reinterpret_cast<float*>(smem + RBUF_OFF);
    float* Wsm = nullptr;
    float* hT = reinterpret_cast<float*>(smem);              // [BN][66] (reused)
    if constexpr (NC > 0) Wsm = hT + BN * 66;                // [BN][NC] (reused)

    const int tpos = wp * 32 + lane;                          // 0..127
    __syncthreads();
    if (wg > 0) {
        float* p = rbuf + (wg - 1) * QF * 128 + tpos;
        int q = 0;
        #pragma unroll
        for (int mt = 0; mt < 2; mt++)
            #pragma unroll
            for (int nf = 0; nf < NF; nf++)
                #pragma unroll
                for (int k4 = 0; k4 < 4; k4++)
                    p[(q++) * 128] = acc[mt][nf][k4];
    }
    if constexpr (NC > 0) {   // overlap W prefetch with the dump
        #pragma unroll
        for (int it = 0; it < BN * NC / 4 / 512; it++) {
            int idx = tid + it * 512;
            reinterpret_cast<float4*>(Wsm)[idx] =
                reinterpret_cast<const float4*>(Wn)[idx];
        }
    }
    __syncthreads();

    const int gr = lane >> 2;
    const int gc = (lane & 3) * 2;
    if (wg == 0) {
        {   // add the three partner groups
            const float* p = rbuf + tpos;
            int q = 0;
            #pragma unroll
            for (int mt = 0; mt < 2; mt++)
                #pragma unroll
                for (int nf = 0; nf < NF; nf++)
                    #pragma unroll
                    for (int k4 = 0; k4 < 4; k4++) {
                        acc[mt][nf][k4] += p[q * 128] + p[(QF + q) * 128]
                                         + p[(2 * QF + q) * 128];
                        q++;
                    }
        }
        // epilogue values: v = [relu](dinv*(acc + Zs_row) + bias)
        #pragma unroll
        for (int mt = 0; mt < 2; mt++)
            #pragma unroll
            for (int half = 0; half < 2; half++) {
                int rl = wm * 32 + mt * 16 + half * 8 + gr;
                int row = m0 + rl;
                float di = g_dinv[row];
                #pragma unroll
                for (int nf = 0; nf < NF; nf++) {
                    int col = n0c + nf * 8 + gc;
                    float2 z = *reinterpret_cast<const float2*>(
                        &g_Zs[SRC][(size_t)row * BN + col]);
                    float v0 = fmaf(di, acc[mt][nf][half * 2 + 0] + z.x, bias[col]);
                    float v1 = fmaf(di, acc[mt][nf][half * 2 + 1] + z.y, bias[col + 1]);
                    if (RELU) { v0 = fmaxf(v0, 0.f); v1 = fmaxf(v1, 0.f); }
                    if constexpr (NC == 0) {
                        *reinterpret_cast<float2*>(&Out[(size_t)row * BN + col]) =
                            make_float2(v0, v1);
                    } else {
                        hT[col * 66 + rl] = v0;
                        hT[(col + 1) * 66 + rl] = v1;
                    }
                }
            }
    }

    if constexpr (NC > 0) {
        __syncthreads();
        // fused feat-GEMM: Zs_next = dinv ⊙ (h @ W), vectorized W loads
        constexpr int CGRP = NC / 8;               // col groups of 8
        constexpr int RT = 64 * CGRP / 512;        // rows per thread (2 or 1)
        const int tx = tid % CGRP;
        const int ty = tid / CGRP;
        float a2[RT][8];
        #pragma unroll
        for (int r = 0; r < RT; r++)
            #pragma unroll
            for (int c = 0; c < 8; c++) a2[r][c] = 0.f;
        #pragma unroll 2
        for (int k = 0; k < BN; k++) {
            float4 w0 = *reinterpret_cast<const float4*>(&Wsm[k * NC + tx * 8]);
            float4 w1 = *reinterpret_cast<const float4*>(&Wsm[k * NC + tx * 8 + 4]);
            #pragma unroll
            for (int r = 0; r < RT; r++) {
                float h = hT[k * 66 + ty * RT + r];
                a2[r][0] = fmaf(h, w0.x, a2[r][0]);
                a2[r][1] = fmaf(h, w0.y, a2[r][1]);
                a2[r][2] = fmaf(h, w0.z, a2[r][2]);
                a2[r][3] = fmaf(h, w0.w, a2[r][3]);
                a2[r][4] = fmaf(h, w1.x, a2[r][4]);
                a2[r][5] = fmaf(h, w1.y, a2[r][5]);
                a2[r][6] = fmaf(h, w1.z, a2[r][6]);
                a2[r][7] = fmaf(h, w1.w, a2[r][7]);
            }
        }
        constexpr int DST = 1 - SRC;
        #pragma unroll
        for (int r = 0; r < RT; r++) {
            int row = m0 + ty * RT + r;
            float di = g_dinv[row];
            float zv[8];
            #pragma unroll
            for (int c = 0; c < 8; c++) zv[c] = di * a2[r][c];
            #pragma unroll
            for (int c = 0; c < 8; c += 4)
                *reinterpret_cast<float4*>(&g_Zs[DST][(size_t)row * NC + tx * 8 + c]) =
                    make_float4(zv[c], zv[c + 1], zv[c + 2], zv[c + 3]);
            #pragma unroll
            for (int c = 0; c < 8; c++)
                g_Bh[DST][(size_t)(tx * 8 + c) * GN + row] = __float2half_rn(zv[c]);
        }
    }
}

// ---------------------------------------------------------------------------
// Launch: 3-layer GCN
// ---------------------------------------------------------------------------
extern "C" void kernel_launch(void* const* d_in, const int* in_sizes, int n_in,
                              void* d_out, int out_size) {
    const float* x   = (const float*)d_in[0];
    const float* adj = (const float*)d_in[1];
    const float* W0  = (const float*)d_in[2];
    const float* b0  = (const float*)d_in[3];
    const float* W1  = (const float*)d_in[4];
    const float* b1  = (const float*)d_in[5];
    const float* W2  = (const float*)d_in[6];
    const float* b2  = (const float*)d_in[7];
    float* out = (float*)d_out;

    // smem = max(4-stage mainloop, fused-epilogue hT+W) + reduction buffer
    const int MAIN128 = 4 * (8192 + 128 * 64 * 2);               // 98304
    const int MAIN64  = 4 * (8192 + 64 * 64 * 2);                // 65536
    const int EPI1 = 128 * 66 * 4 + 128 * 128 * 4;               // 99328
    const int EPI2 = 128 * 66 * 4 + 128 * 64 * 4;                // 66560
    const int RB128 = 3 * 64 * 128 * 4;                          // 98304
    const int RB64  = 3 * 32 * 128 * 4;                          // 49152
    const int SM_L1 = ((MAIN128 > EPI1) ? MAIN128 : EPI1) + RB128;  // 197632
    const int SM_L2 = ((MAIN128 > EPI2) ? MAIN128 : EPI2) + RB128;  // 196608
    const int SM_L3 = MAIN64 + RB64;                                // 114688
    cudaFuncSetAttribute(spmm_hmma<128, 128, 0, true>,
                         cudaFuncAttributeMaxDynamicSharedMemorySize, SM_L1);
    cudaFuncSetAttribute(spmm_hmma<128, 64, 1, true>,
                         cudaFuncAttributeMaxDynamicSharedMemorySize, SM_L2);
    cudaFuncSetAttribute(spmm_hmma<64, 0, 0, false>,
                         cudaFuncAttributeMaxDynamicSharedMemorySize, SM_L3);

    convert_rowsum<<<GN, 256>>>(adj);

    // layer 0 feat: Zs1 = dinv ⊙ (x@W0)  -> buffer 0
    feat_gemm<64, 128><<<GN / 64, 256>>>(x, W0);

    // layer 1: h1 = relu(An@Zs1 + b0); fused: Zs2 = dinv ⊙ (h1@W1) -> buffer 1
    spmm_hmma<128, 128, 0, true><<<GN / 64, 512, SM_L1>>>(b0, W1, nullptr);

    // layer 2: h2 = relu(An@Zs2 + b1); fused: Zs3 = dinv ⊙ (h2@W2) -> buffer 0
    spmm_hmma<128, 64, 1, true><<<GN / 64, 512, SM_L2>>>(b1, W2, nullptr);

    // layer 3: out = An@Zs3 + b2
    spmm_hmma<64, 0, 0, false><<<GN / 64, 512, SM_L3>>>(b2, nullptr, out);
}

// round 16
// speedup vs baseline: 1.0988x; 1.0988x over previous
#include <cuda_runtime.h>
#include <cuda_fp16.h>
#include <cstdint>

#define GN 8192

// ---------------------------------------------------------------------------
// Device-global scratch (allocation-free per harness rules)
// ---------------------------------------------------------------------------
__device__ float g_dinv[GN];
__device__ __half g_adj_h[(size_t)GN * GN];           // fp16 adj, 128 MB
// double-buffered per layer (ping-pong): fp32 Zs + transposed fp16 plane [n][k]
__device__ float g_Zs[2][(size_t)GN * 128];
__device__ __half g_Bh[2][(size_t)128 * GN];

// ---------------------------------------------------------------------------
// PTX helpers (compute_103-safe: cp.async + ldmatrix + mma.sync only)
// ---------------------------------------------------------------------------
__device__ __forceinline__ uint32_t smem_u32(const void* p) {
    uint32_t a;
    asm("{ .reg .u64 t; cvta.to.shared.u64 t, %1; cvt.u32.u64 %0, t; }" : "=r"(a) : "l"(p));
    return a;
}
__device__ __forceinline__ void cp16(uint32_t dst, const void* src) {
    asm volatile("cp.async.cg.shared.global [%0], [%1], 16;" :: "r"(dst), "l"(src));
}
__device__ __forceinline__ void cp_commit() { asm volatile("cp.async.commit_group;" ::: "memory"); }
template<int N>
__device__ __forceinline__ void cp_wait() { asm volatile("cp.async.wait_group %0;" :: "n"(N) : "memory"); }

__device__ __forceinline__ void ldsm4(uint32_t* r, uint32_t addr) {
    asm volatile("ldmatrix.sync.aligned.m8n8.x4.shared.b16 {%0,%1,%2,%3}, [%4];"
                 : "=r"(r[0]), "=r"(r[1]), "=r"(r[2]), "=r"(r[3]) : "r"(addr));
}
__device__ __forceinline__ void mma_f16(float* d, const uint32_t* a, const uint32_t* b) {
    asm volatile("mma.sync.aligned.m16n8k16.row.col.f32.f16.f16.f32 "
                 "{%0,%1,%2,%3}, {%4,%5,%6,%7}, {%8,%9}, {%0,%1,%2,%3};"
                 : "+f"(d[0]), "+f"(d[1]), "+f"(d[2]), "+f"(d[3])
                 : "r"(a[0]), "r"(a[1]), "r"(a[2]), "r"(a[3]), "r"(b[0]), "r"(b[1]));
}

// ---------------------------------------------------------------------------
// Kernel 1: rowsum (fp32-exact) + fp32 -> fp16 convert of adj (fused one pass)
// ---------------------------------------------------------------------------
__global__ void __launch_bounds__(256) convert_rowsum(const float* __restrict__ adj) {
    int row = blockIdx.x;
    int tid = threadIdx.x;
    const float4* src = reinterpret_cast<const float4*>(adj + (size_t)row * GN);
    uint4* dst = reinterpret_cast<uint4*>(g_adj_h + (size_t)row * GN);
    float s = 0.f;
    #pragma unroll
    for (int i = tid; i < GN / 8; i += 256) {
        float4 v0 = src[2 * i];
        float4 v1 = src[2 * i + 1];
        s += ((v0.x + v0.y) + (v0.z + v0.w)) + ((v1.x + v1.y) + (v1.z + v1.w));
        __half2 p0 = __floats2half2_rn(v0.x, v0.y);
        __half2 p1 = __floats2half2_rn(v0.z, v0.w);
        __half2 p2 = __floats2half2_rn(v1.x, v1.y);
        __half2 p3 = __floats2half2_rn(v1.z, v1.w);
        uint4 u;
        u.x = *reinterpret_cast<uint32_t*>(&p0);
        u.y = *reinterpret_cast<uint32_t*>(&p1);
        u.z = *reinterpret_cast<uint32_t*>(&p2);
        u.w = *reinterpret_cast<uint32_t*>(&p3);
        dst[i] = u;
    }
    __shared__ float red[8];
    #pragma unroll
    for (int o = 16; o; o >>= 1) s += __shfl_down_sync(0xffffffffu, s, o);
    if ((tid & 31) == 0) red[tid >> 5] = s;
    __syncthreads();
    if (tid == 0) {
        float t = 0.f;
        #pragma unroll
        for (int w = 0; w < 8; w++) t += red[w];
        g_dinv[row] = rsqrtf(t + 1.0f);
    }
}

// ---------------------------------------------------------------------------
// Kernel 2 (layer 0 only): Zs = dinv ⊙ (x @ W0) -> buffer 0 (fp32 + fp16 plane)
// ---------------------------------------------------------------------------
template<int K, int NC>
__global__ void __launch_bounds__(256) feat_gemm(const float* __restrict__ Xin,
                                                 const float* __restrict__ W) {
    constexpr int CW = NC / 16;
    __shared__ float hs[64][K];
    __shared__ float ws[16][NC];
    int tid = threadIdx.x;
    int r0 = blockIdx.x * 64;
    int tx = tid & 15, ty = tid >> 4;

    {
        const float4* s4 = reinterpret_cast<const float4*>(Xin + (size_t)r0 * K);
        float4* d4 = reinterpret_cast<float4*>(&hs[0][0]);
        for (int i = tid; i < 64 * K / 4; i += 256) d4[i] = s4[i];
    }
    float acc[4][CW];
    #pragma unroll
    for (int r = 0; r < 4; r++)
        #pragma unroll
        for (int c = 0; c < CW; c++) acc[r][c] = 0.f;

    for (int kc = 0; kc < K / 16; kc++) {
        __syncthreads();
        {
            const float4* s4 = reinterpret_cast<const float4*>(W + kc * 16 * NC);
            float4* d4 = reinterpret_cast<float4*>(&ws[0][0]);
            for (int i = tid; i < 16 * NC / 4; i += 256) d4[i] = s4[i];
        }
        __syncthreads();
        #pragma unroll
        for (int k = 0; k < 16; k++) {
            float a0 = hs[ty * 4 + 0][kc * 16 + k];
            float a1 = hs[ty * 4 + 1][kc * 16 + k];
            float a2 = hs[ty * 4 + 2][kc * 16 + k];
            float a3 = hs[ty * 4 + 3][kc * 16 + k];
            #pragma unroll
            for (int c = 0; c < CW; c++) {
                float w = ws[k][c * 16 + tx];
                acc[0][c] = fmaf(a0, w, acc[0][c]);
                acc[1][c] = fmaf(a1, w, acc[1][c]);
                acc[2][c] = fmaf(a2, w, acc[2][c]);
                acc[3][c] = fmaf(a3, w, acc[3][c]);
            }
        }
    }
    #pragma unroll
    for (int r = 0; r < 4; r++) {
        int row = r0 + ty * 4 + r;
        float di = g_dinv[row];
        #pragma unroll
        for (int c = 0; c < CW; c++) {
            int col = c * 16 + tx;
            float z = di * acc[r][c];
            g_Zs[0][(size_t)row * NC + col] = z;
            g_Bh[0][(size_t)col * GN + row] = __float2half_rn(z);
        }
    }
}

// ---------------------------------------------------------------------------
// Kernel 3: single-pass fp16 HMMA SpMM + fused epilogue
//   h = [relu]( dinv[i]*( adj_h@Bh + Zs[i,:] ) + bias )
//   If NC>0: also computes next layer's Zs = dinv ⊙ (h @ W) in-kernel.
//   BM=64 (128 CTAs), 512 threads = 16 warps:
//     8 warp positions (2m x 4n), each a 32x(BN/4) tile;
//     2-way K-split across warp groups (wg = warp>>3), reduced at the end.
//   BK=128, 4-stage cp.async (4 k16 steps per warp between barriers).
//   smem rows 256B (16 chunks); swizzle: chunk' = c ^ (row & 7).
// ---------------------------------------------------------------------------
template<int BN, int NC, int SRC, bool RELU>
__global__ void __launch_bounds__(512) spmm_hmma(const float* __restrict__ bias,
                                                 const float* __restrict__ Wn,
                                                 float* __restrict__ Out) {
    constexpr int BK = 128;
    constexpr int NT = GN / BK;               // 64 k-tiles
    constexpr int ASZ = 64 * BK * 2;          // 16 KB fp16 A plane
    constexpr int BSZ = BN * BK * 2;          // fp16 B plane (32 or 16 KB)
    constexpr int STAGE = ASZ + BSZ;
    constexpr int WN = BN / 4;                // warp-position n extent (32 or 16)
    constexpr int NF = WN / 8;                // n8 fragments (4 or 2)
    constexpr int RB = 2 * NF * 4;            // accum floats per thread
    constexpr int EPIH = (NC > 0) ? (BN * 66 * 4 + BN * NC * 4) : 0;
    constexpr int MAINSZ = 4 * STAGE;
    constexpr int RBUF_OFF = (MAINSZ > EPIH) ? MAINSZ : EPIH;

    extern __shared__ char smem[];
    const uint32_t sb0 = smem_u32(smem);

    const int tid = threadIdx.x;
    const int lane = tid & 31;
    const int warp = tid >> 5;
    const int wg = warp >> 3;                 // k-split group 0/1
    const int wp = warp & 7;                  // warp position
    const int wm = wp >> 2;                   // 0..1 (32 rows each)
    const int wn = wp & 3;
    const int m0 = blockIdx.x * 64;
    const int n0c = wn * WN;

    float acc[2][NF][4];
    #pragma unroll
    for (int mt = 0; mt < 2; mt++)
        #pragma unroll
        for (int nf = 0; nf < NF; nf++)
            #pragma unroll
            for (int q = 0; q < 4; q++) acc[mt][nf][q] = 0.f;

    auto issue = [&](int kt) {
        if (kt < NT) {
            const uint32_t sb = sb0 + (kt & 3) * STAGE;
            const int k0 = kt * BK;
            #pragma unroll
            for (int j = 0; j < 2; j++) {        // A: 64 rows x 16 chunks = 1024
                int id = tid + j * 512;
                int row = id >> 4, c = id & 15;
                uint32_t so = row * 256 + ((c ^ (row & 7)) << 4);
                cp16(sb + so, g_adj_h + (size_t)(m0 + row) * GN + k0 + c * 8);
            }
            #pragma unroll
            for (int j = 0; j < BN / 32; j++) {  // B: BN rows x 16 chunks
                int idx = tid + j * 512;
                int row = idx >> 4, c = idx & 15;
                uint32_t so = row * 256 + ((c ^ (row & 7)) << 4);
                cp16(sb + ASZ + so, g_Bh[SRC] + (size_t)row * GN + k0 + c * 8);
            }
        }
        cp_commit();
    };

    issue(0); issue(1); issue(2);

    #pragma unroll 1
    for (int kt = 0; kt < NT; kt++) {
        cp_wait<2>();
        __syncthreads();
        issue(kt + 3);            // refills slot (kt-1)&3, safe post-sync

        const uint32_t sb = sb0 + (kt & 3) * STAGE;
        #pragma unroll
        for (int s = 0; s < 4; s++) {          // this warp-group's k16 steps
            const int kc = wg * 8 + s * 2;     // base 16B-chunk of this k16
            uint32_t af[2][4];
            #pragma unroll
            for (int mt = 0; mt < 2; mt++) {
                int row = wm * 32 + mt * 16 + (lane & 15);
                int ch = (kc + (lane >> 4)) ^ (row & 7);
                ldsm4(af[mt], sb + row * 256 + ch * 16);
            }
            uint32_t bf[NF][2];
            #pragma unroll
            for (int bt = 0; bt < NF / 2; bt++) {
                int row = n0c + bt * 16 + (lane & 7) + ((lane >> 4) << 3);
                int ch = (kc + ((lane >> 3) & 1)) ^ (row & 7);
                uint32_t t[4];
                ldsm4(t, sb + ASZ + row * 256 + ch * 16);
                bf[2 * bt][0] = t[0]; bf[2 * bt][1] = t[1];
                bf[2 * bt + 1][0] = t[2]; bf[2 * bt + 1][1] = t[3];
            }
            #pragma unroll
            for (int mt = 0; mt < 2; mt++)
                #pragma unroll
                for (int nf = 0; nf < NF; nf++)
                    mma_f16(acc[mt][nf], af[mt], bf[nf]);
        }
    }

    // ---- K-split reduction: wg1 dumps accumulators, wg0 adds ----
    float* rbuf = reinterpret_cast<float*>(smem + RBUF_OFF);
    __syncthreads();
    if (wg == 1) {
        float* p = rbuf + (wp * 32 + lane) * (RB + 1);
        #pragma unroll
        for (int mt = 0; mt < 2; mt++)
            #pragma unroll
            for (int nf = 0; nf < NF; nf++)
                #pragma unroll
                for (int q = 0; q < 4; q++)
                    p[mt * NF * 4 + nf * 4 + q] = acc[mt][nf][q];
    }
    __syncthreads();
    if (wg == 0) {
        const float* p = rbuf + (wp * 32 + lane) * (RB + 1);
        #pragma unroll
        for (int mt = 0; mt < 2; mt++)
            #pragma unroll
            for (int nf = 0; nf < NF; nf++)
                #pragma unroll
                for (int q = 0; q < 4; q++)
                    acc[mt][nf][q] += p[mt * NF * 4 + nf * 4 + q];
    }
    __syncthreads();   // rbuf + stage smem free for reuse below

    // ---- epilogue: h = [relu](dinv*(acc + Zs_row) + bias) (wg0 warps hold sums)
    const int gr = lane >> 2;
    const int gc = (lane & 3) * 2;

    if constexpr (NC == 0) {
        if (wg == 0) {
            #pragma unroll
            for (int mt = 0; mt < 2; mt++)
                #pragma unroll
                for (int half = 0; half < 2; half++) {
                    int row = m0 + wm * 32 + mt * 16 + half * 8 + gr;
                    float di = g_dinv[row];
                    #pragma unroll
                    for (int nf = 0; nf < NF; nf++) {
                        int col = n0c + nf * 8 + gc;
                        float2 z = *reinterpret_cast<const float2*>(
                            &g_Zs[SRC][(size_t)row * BN + col]);
                        float v0 = fmaf(di, acc[mt][nf][half * 2 + 0] + z.x, bias[col]);
                        float v1 = fmaf(di, acc[mt][nf][half * 2 + 1] + z.y, bias[col + 1]);
                        if (RELU) { v0 = fmaxf(v0, 0.f); v1 = fmaxf(v1, 0.f); }
                        *reinterpret_cast<float2*>(&Out[(size_t)row * BN + col]) =
                            make_float2(v0, v1);
                    }
                }
        }
    } else {
        // fused feat-GEMM: hT[col][row] in smem (pad 66), W in smem, then h@W
        float* hT = reinterpret_cast<float*>(smem);          // [BN][66]
        float* Wsm = hT + BN * 66;                           // [BN][NC]
        if (wg == 0) {
            #pragma unroll
            for (int mt = 0; mt < 2; mt++)
                #pragma unroll
                for (int half = 0; half < 2; half++) {
                    int rl = wm * 32 + mt * 16 + half * 8 + gr;
                    int row = m0 + rl;
                    float di = g_dinv[row];
                    #pragma unroll
                    for (int nf = 0; nf < NF; nf++) {
                        int col = n0c + nf * 8 + gc;
                        float2 z = *reinterpret_cast<const float2*>(
                            &g_Zs[SRC][(size_t)row * BN + col]);
                        float v0 = fmaf(di, acc[mt][nf][half * 2 + 0] + z.x, bias[col]);
                        float v1 = fmaf(di, acc[mt][nf][half * 2 + 1] + z.y, bias[col + 1]);
                        if (RELU) { v0 = fmaxf(v0, 0.f); v1 = fmaxf(v1, 0.f); }
                        hT[col * 66 + rl] = v0;
                        hT[(col + 1) * 66 + rl] = v1;
                    }
                }
        }
        #pragma unroll
        for (int it = 0; it < BN * NC / 4 / 512; it++) {
            int idx = tid + it * 512;
            reinterpret_cast<float4*>(Wsm)[idx] =
                reinterpret_cast<const float4*>(Wn)[idx];
        }
        __syncthreads();

        constexpr int CW = NC / 16;
        const int tx = tid & 15, ty = tid >> 4;   // 2 rows/thread, CW cols
        float a2[2][CW];
        #pragma unroll
        for (int r = 0; r < 2; r++)
            #pragma unroll
            for (int c = 0; c < CW; c++) a2[r][c] = 0.f;
        #pragma unroll 4
        for (int k = 0; k < BN; k++) {
            float h0 = hT[k * 66 + 2 * ty];
            float h1 = hT[k * 66 + 2 * ty + 1];
            #pragma unroll
            for (int c = 0; c < CW; c++) {
                float w = Wsm[k * NC + c * 16 + tx];
                a2[0][c] = fmaf(h0, w, a2[0][c]);
                a2[1][c] = fmaf(h1, w, a2[1][c]);
            }
        }
        constexpr int DST = 1 - SRC;
        #pragma unroll
        for (int r = 0; r < 2; r++) {
            int row = m0 + 2 * ty + r;
            float di = g_dinv[row];
            #pragma unroll
            for (int c = 0; c < CW; c++) {
                int col = c * 16 + tx;
                float z = di * a2[r][c];
                g_Zs[DST][(size_t)row * NC + col] = z;
                g_Bh[DST][(size_t)col * GN + row] = __float2half_rn(z);
            }
        }
    }
}

// ---------------------------------------------------------------------------
// Launch: 3-layer GCN
// ---------------------------------------------------------------------------
extern "C" void kernel_launch(void* const* d_in, const int* in_sizes, int n_in,
                              void* d_out, int out_size) {
    const float* x   = (const float*)d_in[0];
    const float* adj = (const float*)d_in[1];
    const float* W0  = (const float*)d_in[2];
    const float* b0  = (const float*)d_in[3];
    const float* W1  = (const float*)d_in[4];
    const float* b1  = (const float*)d_in[5];
    const float* W2  = (const float*)d_in[6];
    const float* b2  = (const float*)d_in[7];
    float* out = (float*)d_out;

    // smem = max(4-stage BK=128 mainloop, fused-epilogue hT+W) + reduction buf
    const int MAIN128 = 4 * (16384 + 128 * 128 * 2);             // 196608
    const int MAIN64  = 4 * (16384 + 64 * 128 * 2);              // 131072
    const int EPI1 = 128 * 66 * 4 + 128 * 128 * 4;               // 99328
    const int EPI2 = 128 * 66 * 4 + 128 * 64 * 4;                // 66560
    const int RB128 = 8 * 32 * 33 * 4;                           // 33792
    const int RB64  = 8 * 32 * 17 * 4;                           // 17408
    const int SM_L1 = ((MAIN128 > EPI1) ? MAIN128 : EPI1) + RB128;  // 230400
    const int SM_L2 = ((MAIN128 > EPI2) ? MAIN128 : EPI2) + RB128;  // 230400
    const int SM_L3 = MAIN64 + RB64;                                // 148480
    cudaFuncSetAttribute(spmm_hmma<128, 128, 0, true>,
                         cudaFuncAttributeMaxDynamicSharedMemorySize, SM_L1);
    cudaFuncSetAttribute(spmm_hmma<128, 64, 1, true>,
                         cudaFuncAttributeMaxDynamicSharedMemorySize, SM_L2);
    cudaFuncSetAttribute(spmm_hmma<64, 0, 0, false>,
                         cudaFuncAttributeMaxDynamicSharedMemorySize, SM_L3);

    convert_rowsum<<<GN, 256>>>(adj);

    // layer 0 feat: Zs1 = dinv ⊙ (x@W0)  -> buffer 0
    feat_gemm<64, 128><<<GN / 64, 256>>>(x, W0);

    // layer 1: h1 = relu(An@Zs1 + b0); fused: Zs2 = dinv ⊙ (h1@W1) -> buffer 1
    spmm_hmma<128, 128, 0, true><<<GN / 64, 512, SM_L1>>>(b0, W1, nullptr);

    // layer 2: h2 = relu(An@Zs2 + b1); fused: Zs3 = dinv ⊙ (h2@W2) -> buffer 0
    spmm_hmma<128, 64, 1, true><<<GN / 64, 512, SM_L2>>>(b1, W2, nullptr);

    // layer 3: out = An@Zs3 + b2
    spmm_hmma<64, 0, 0, false><<<GN / 64, 512, SM_L3>>>(b2, nullptr, out);
}

// round 17
// speedup vs baseline: 1.1071x; 1.0076x over previous
#include <cuda_runtime.h>
#include <cuda_fp16.h>
#include <cstdint>

#define GN 8192

// ---------------------------------------------------------------------------
// Device-global scratch (allocation-free per harness rules)
// ---------------------------------------------------------------------------
__device__ float g_dinv[GN];
__device__ __half g_adj_h[(size_t)GN * GN];           // fp16 adj, 128 MB
// double-buffered per layer (ping-pong): fp32 Zs + transposed fp16 plane [n][k]
__device__ float g_Zs[2][(size_t)GN * 128];
__device__ __half g_Bh[2][(size_t)128 * GN];

// ---------------------------------------------------------------------------
// PTX helpers (compute_103-safe: cp.async + ldmatrix + mma.sync only)
// ---------------------------------------------------------------------------
__device__ __forceinline__ uint32_t smem_u32(const void* p) {
    uint32_t a;
    asm("{ .reg .u64 t; cvta.to.shared.u64 t, %1; cvt.u32.u64 %0, t; }" : "=r"(a) : "l"(p));
    return a;
}
__device__ __forceinline__ void cp16(uint32_t dst, const void* src) {
    asm volatile("cp.async.cg.shared.global [%0], [%1], 16;" :: "r"(dst), "l"(src));
}
__device__ __forceinline__ void cp_commit() { asm volatile("cp.async.commit_group;" ::: "memory"); }
template<int N>
__device__ __forceinline__ void cp_wait() { asm volatile("cp.async.wait_group %0;" :: "n"(N) : "memory"); }

__device__ __forceinline__ void ldsm4(uint32_t* r, uint32_t addr) {
    asm volatile("ldmatrix.sync.aligned.m8n8.x4.shared.b16 {%0,%1,%2,%3}, [%4];"
                 : "=r"(r[0]), "=r"(r[1]), "=r"(r[2]), "=r"(r[3]) : "r"(addr));
}
__device__ __forceinline__ void mma_f16(float* d, const uint32_t* a, const uint32_t* b) {
    asm volatile("mma.sync.aligned.m16n8k16.row.col.f32.f16.f16.f32 "
                 "{%0,%1,%2,%3}, {%4,%5,%6,%7}, {%8,%9}, {%0,%1,%2,%3};"
                 : "+f"(d[0]), "+f"(d[1]), "+f"(d[2]), "+f"(d[3])
                 : "r"(a[0]), "r"(a[1]), "r"(a[2]), "r"(a[3]), "r"(b[0]), "r"(b[1]));
}

// ---------------------------------------------------------------------------
// Kernel 1: rowsum (fp32-exact) + fp32 -> fp16 convert of adj (fused one pass)
// ---------------------------------------------------------------------------
__global__ void __launch_bounds__(256) convert_rowsum(const float* __restrict__ adj) {
    int row = blockIdx.x;
    int tid = threadIdx.x;
    const float4* src = reinterpret_cast<const float4*>(adj + (size_t)row * GN);
    uint4* dst = reinterpret_cast<uint4*>(g_adj_h + (size_t)row * GN);
    float s = 0.f;
    #pragma unroll
    for (int i = tid; i < GN / 8; i += 256) {
        float4 v0 = src[2 * i];
        float4 v1 = src[2 * i + 1];
        s += ((v0.x + v0.y) + (v0.z + v0.w)) + ((v1.x + v1.y) + (v1.z + v1.w));
        __half2 p0 = __floats2half2_rn(v0.x, v0.y);
        __half2 p1 = __floats2half2_rn(v0.z, v0.w);
        __half2 p2 = __floats2half2_rn(v1.x, v1.y);
        __half2 p3 = __floats2half2_rn(v1.z, v1.w);
        uint4 u;
        u.x = *reinterpret_cast<uint32_t*>(&p0);
        u.y = *reinterpret_cast<uint32_t*>(&p1);
        u.z = *reinterpret_cast<uint32_t*>(&p2);
        u.w = *reinterpret_cast<uint32_t*>(&p3);
        dst[i] = u;
    }
    __shared__ float red[8];
    #pragma unroll
    for (int o = 16; o; o >>= 1) s += __shfl_down_sync(0xffffffffu, s, o);
    if ((tid & 31) == 0) red[tid >> 5] = s;
    __syncthreads();
    if (tid == 0) {
        float t = 0.f;
        #pragma unroll
        for (int w = 0; w < 8; w++) t += red[w];
        g_dinv[row] = rsqrtf(t + 1.0f);
    }
}

// ---------------------------------------------------------------------------
// Kernel 2 (layer 0 only): Zs = dinv ⊙ (x @ W0) -> buffer 0 (fp32 + fp16 plane)
// ---------------------------------------------------------------------------
template<int K, int NC>
__global__ void __launch_bounds__(256) feat_gemm(const float* __restrict__ Xin,
                                                 const float* __restrict__ W) {
    constexpr int CW = NC / 16;
    __shared__ float hs[64][K];
    __shared__ float ws[16][NC];
    int tid = threadIdx.x;
    int r0 = blockIdx.x * 64;
    int tx = tid & 15, ty = tid >> 4;

    {
        const float4* s4 = reinterpret_cast<const float4*>(Xin + (size_t)r0 * K);
        float4* d4 = reinterpret_cast<float4*>(&hs[0][0]);
        for (int i = tid; i < 64 * K / 4; i += 256) d4[i] = s4[i];
    }
    float acc[4][CW];
    #pragma unroll
    for (int r = 0; r < 4; r++)
        #pragma unroll
        for (int c = 0; c < CW; c++) acc[r][c] = 0.f;

    for (int kc = 0; kc < K / 16; kc++) {
        __syncthreads();
        {
            const float4* s4 = reinterpret_cast<const float4*>(W + kc * 16 * NC);
            float4* d4 = reinterpret_cast<float4*>(&ws[0][0]);
            for (int i = tid; i < 16 * NC / 4; i += 256) d4[i] = s4[i];
        }
        __syncthreads();
        #pragma unroll
        for (int k = 0; k < 16; k++) {
            float a0 = hs[ty * 4 + 0][kc * 16 + k];
            float a1 = hs[ty * 4 + 1][kc * 16 + k];
            float a2 = hs[ty * 4 + 2][kc * 16 + k];
            float a3 = hs[ty * 4 + 3][kc * 16 + k];
            #pragma unroll
            for (int c = 0; c < CW; c++) {
                float w = ws[k][c * 16 + tx];
                acc[0][c] = fmaf(a0, w, acc[0][c]);
                acc[1][c] = fmaf(a1, w, acc[1][c]);
                acc[2][c] = fmaf(a2, w, acc[2][c]);
                acc[3][c] = fmaf(a3, w, acc[3][c]);
            }
        }
    }
    #pragma unroll
    for (int r = 0; r < 4; r++) {
        int row = r0 + ty * 4 + r;
        float di = g_dinv[row];
        #pragma unroll
        for (int c = 0; c < CW; c++) {
            int col = c * 16 + tx;
            float z = di * acc[r][c];
            g_Zs[0][(size_t)row * NC + col] = z;
            g_Bh[0][(size_t)col * GN + row] = __float2half_rn(z);
        }
    }
}

// ---------------------------------------------------------------------------
// Kernel 3: single-pass fp16 HMMA SpMM + fused epilogue
//   h = [relu]( dinv[i]*( adj_h@Bh + Zs[i,:] ) + bias )
//   If NC>0: also computes next layer's Zs = dinv ⊙ (h @ W) in-kernel.
//   BM=64 (128 CTAs), 512 threads = 16 warps:
//     8 warp positions (2m x 4n), each a 32x(BN/4) tile;
//     2-way K-split across warp groups (wg = warp>>3), reduced at the end.
//   BK=128, 4-stage cp.async, register double-buffered fragments:
//     ldsm for k16 step s+1 issued before the MMAs of step s (latency hiding).
//   smem rows 256B (16 chunks); swizzle: chunk' = c ^ (row & 7).
// ---------------------------------------------------------------------------
template<int BN, int NC, int SRC, bool RELU>
__global__ void __launch_bounds__(512) spmm_hmma(const float* __restrict__ bias,
                                                 const float* __restrict__ Wn,
                                                 float* __restrict__ Out) {
    constexpr int BK = 128;
    constexpr int NT = GN / BK;               // 64 k-tiles
    constexpr int ASZ = 64 * BK * 2;          // 16 KB fp16 A plane
    constexpr int BSZ = BN * BK * 2;          // fp16 B plane (32 or 16 KB)
    constexpr int STAGE = ASZ + BSZ;
    constexpr int WN = BN / 4;                // warp-position n extent (32 or 16)
    constexpr int NF = WN / 8;                // n8 fragments (4 or 2)
    constexpr int RB = 2 * NF * 4;            // accum floats per thread
    constexpr int EPIH = (NC > 0) ? (BN * 66 * 4 + BN * NC * 4) : 0;
    constexpr int MAINSZ = 4 * STAGE;
    constexpr int RBUF_OFF = (MAINSZ > EPIH) ? MAINSZ : EPIH;

    extern __shared__ char smem[];
    const uint32_t sb0 = smem_u32(smem);

    const int tid = threadIdx.x;
    const int lane = tid & 31;
    const int warp = tid >> 5;
    const int wg = warp >> 3;                 // k-split group 0/1
    const int wp = warp & 7;                  // warp position
    const int wm = wp >> 2;                   // 0..1 (32 rows each)
    const int wn = wp & 3;
    const int m0 = blockIdx.x * 64;
    const int n0c = wn * WN;

    float acc[2][NF][4];
    #pragma unroll
    for (int mt = 0; mt < 2; mt++)
        #pragma unroll
        for (int nf = 0; nf < NF; nf++)
            #pragma unroll
            for (int q = 0; q < 4; q++) acc[mt][nf][q] = 0.f;

    auto issue = [&](int kt) {
        if (kt < NT) {
            const uint32_t sb = sb0 + (kt & 3) * STAGE;
            const int k0 = kt * BK;
            #pragma unroll
            for (int j = 0; j < 2; j++) {        // A: 64 rows x 16 chunks = 1024
                int id = tid + j * 512;
                int row = id >> 4, c = id & 15;
                uint32_t so = row * 256 + ((c ^ (row & 7)) << 4);
                cp16(sb + so, g_adj_h + (size_t)(m0 + row) * GN + k0 + c * 8);
            }
            #pragma unroll
            for (int j = 0; j < BN / 32; j++) {  // B: BN rows x 16 chunks
                int idx = tid + j * 512;
                int row = idx >> 4, c = idx & 15;
                uint32_t so = row * 256 + ((c ^ (row & 7)) << 4);
                cp16(sb + ASZ + so, g_Bh[SRC] + (size_t)row * GN + k0 + c * 8);
            }
        }
        cp_commit();
    };

    issue(0); issue(1); issue(2);

    // register double-buffered fragments
    uint32_t af[2][2][4];
    uint32_t bf[2][NF][2];

    #pragma unroll 1
    for (int kt = 0; kt < NT; kt++) {
        cp_wait<2>();
        __syncthreads();
        issue(kt + 3);            // refills slot (kt-1)&3, safe post-sync

        const uint32_t sb = sb0 + (kt & 3) * STAGE;

        auto load_frags = [&](int s, int buf) {
            const int kc = wg * 8 + s * 2;       // base 16B-chunk of k16 step s
            #pragma unroll
            for (int mt = 0; mt < 2; mt++) {
                int row = wm * 32 + mt * 16 + (lane & 15);
                int ch = (kc + (lane >> 4)) ^ (row & 7);
                ldsm4(af[buf][mt], sb + row * 256 + ch * 16);
            }
            #pragma unroll
            for (int bt = 0; bt < NF / 2; bt++) {
                int row = n0c + bt * 16 + (lane & 7) + ((lane >> 4) << 3);
                int ch = (kc + ((lane >> 3) & 1)) ^ (row & 7);
                uint32_t t[4];
                ldsm4(t, sb + ASZ + row * 256 + ch * 16);
                bf[buf][2 * bt][0] = t[0]; bf[buf][2 * bt][1] = t[1];
                bf[buf][2 * bt + 1][0] = t[2]; bf[buf][2 * bt + 1][1] = t[3];
            }
        };

        load_frags(0, 0);
        #pragma unroll
        for (int s = 0; s < 4; s++) {
            if (s < 3) load_frags(s + 1, (s + 1) & 1);   // prefetch next step
            const int cur = s & 1;
            #pragma unroll
            for (int mt = 0; mt < 2; mt++)
                #pragma unroll
                for (int nf = 0; nf < NF; nf++)
                    mma_f16(acc[mt][nf], af[cur][mt], bf[cur][nf]);
        }
    }

    // ---- K-split reduction: wg1 dumps accumulators, wg0 adds ----
    float* rbuf = reinterpret_cast<float*>(smem + RBUF_OFF);
    __syncthreads();
    if (wg == 1) {
        float* p = rbuf + (wp * 32 + lane) * (RB + 1);
        #pragma unroll
        for (int mt = 0; mt < 2; mt++)
            #pragma unroll
            for (int nf = 0; nf < NF; nf++)
                #pragma unroll
                for (int q = 0; q < 4; q++)
                    p[mt * NF * 4 + nf * 4 + q] = acc[mt][nf][q];
    }
    __syncthreads();
    if (wg == 0) {
        const float* p = rbuf + (wp * 32 + lane) * (RB + 1);
        #pragma unroll
        for (int mt = 0; mt < 2; mt++)
            #pragma unroll
            for (int nf = 0; nf < NF; nf++)
                #pragma unroll
                for (int q = 0; q < 4; q++)
                    acc[mt][nf][q] += p[mt * NF * 4 + nf * 4 + q];
    }
    __syncthreads();   // rbuf + stage smem free for reuse below

    // ---- epilogue: h = [relu](dinv*(acc + Zs_row) + bias) (wg0 warps hold sums)
    const int gr = lane >> 2;
    const int gc = (lane & 3) * 2;

    if constexpr (NC == 0) {
        if (wg == 0) {
            #pragma unroll
            for (int mt = 0; mt < 2; mt++)
                #pragma unroll
                for (int half = 0; half < 2; half++) {
                    int row = m0 + wm * 32 + mt * 16 + half * 8 + gr;
                    float di = g_dinv[row];
                    #pragma unroll
                    for (int nf = 0; nf < NF; nf++) {
                        int col = n0c + nf * 8 + gc;
                        float2 z = *reinterpret_cast<const float2*>(
                            &g_Zs[SRC][(size_t)row * BN + col]);
                        float v0 = fmaf(di, acc[mt][nf][half * 2 + 0] + z.x, bias[col]);
                        float v1 = fmaf(di, acc[mt][nf][half * 2 + 1] + z.y, bias[col + 1]);
                        if (RELU) { v0 = fmaxf(v0, 0.f); v1 = fmaxf(v1, 0.f); }
                        *reinterpret_cast<float2*>(&Out[(size_t)row * BN + col]) =
                            make_float2(v0, v1);
                    }
                }
        }
    } else {
        // fused feat-GEMM: hT[col][row] in smem (pad 66), W in smem, then h@W
        float* hT = reinterpret_cast<float*>(smem);          // [BN][66]
        float* Wsm = hT + BN * 66;                           // [BN][NC]
        if (wg == 0) {
            #pragma unroll
            for (int mt = 0; mt < 2; mt++)
                #pragma unroll
                for (int half = 0; half < 2; half++) {
                    int rl = wm * 32 + mt * 16 + half * 8 + gr;
                    int row = m0 + rl;
                    float di = g_dinv[row];
                    #pragma unroll
                    for (int nf = 0; nf < NF; nf++) {
                        int col = n0c + nf * 8 + gc;
                        float2 z = *reinterpret_cast<const float2*>(
                            &g_Zs[SRC][(size_t)row * BN + col]);
                        float v0 = fmaf(di, acc[mt][nf][half * 2 + 0] + z.x, bias[col]);
                        float v1 = fmaf(di, acc[mt][nf][half * 2 + 1] + z.y, bias[col + 1]);
                        if (RELU) { v0 = fmaxf(v0, 0.f); v1 = fmaxf(v1, 0.f); }
                        hT[col * 66 + rl] = v0;
                        hT[(col + 1) * 66 + rl] = v1;
                    }
                }
        }
        #pragma unroll
        for (int it = 0; it < BN * NC / 4 / 512; it++) {
            int idx = tid + it * 512;
            reinterpret_cast<float4*>(Wsm)[idx] =
                reinterpret_cast<const float4*>(Wn)[idx];
        }
        __syncthreads();

        constexpr int CW = NC / 16;
        const int tx = tid & 15, ty = tid >> 4;   // 2 rows/thread, CW cols
        float a2[2][CW];
        #pragma unroll
        for (int r = 0; r < 2; r++)
            #pragma unroll
            for (int c = 0; c < CW; c++) a2[r][c] = 0.f;
        #pragma unroll 4
        for (int k = 0; k < BN; k++) {
            float h0 = hT[k * 66 + 2 * ty];
            float h1 = hT[k * 66 + 2 * ty + 1];
            #pragma unroll
            for (int c = 0; c < CW; c++) {
                float w = Wsm[k * NC + c * 16 + tx];
                a2[0][c] = fmaf(h0, w, a2[0][c]);
                a2[1][c] = fmaf(h1, w, a2[1][c]);
            }
        }
        constexpr int DST = 1 - SRC;
        #pragma unroll
        for (int r = 0; r < 2; r++) {
            int row = m0 + 2 * ty + r;
            float di = g_dinv[row];
            #pragma unroll
            for (int c = 0; c < CW; c++) {
                int col = c * 16 + tx;
                float z = di * a2[r][c];
                g_Zs[DST][(size_t)row * NC + col] = z;
                g_Bh[DST][(size_t)col * GN + row] = __float2half_rn(z);
            }
        }
    }
}

// ---------------------------------------------------------------------------
// Launch: 3-layer GCN
// ---------------------------------------------------------------------------
extern "C" void kernel_launch(void* const* d_in, const int* in_sizes, int n_in,
                              void* d_out, int out_size) {
    const float* x   = (const float*)d_in[0];
    const float* adj = (const float*)d_in[1];
    const float* W0  = (const float*)d_in[2];
    const float* b0  = (const float*)d_in[3];
    const float* W1  = (const float*)d_in[4];
    const float* b1  = (const float*)d_in[5];
    const float* W2  = (const float*)d_in[6];
    const float* b2  = (const float*)d_in[7];
    float* out = (float*)d_out;

    // smem = max(4-stage BK=128 mainloop, fused-epilogue hT+W) + reduction buf
    const int MAIN128 = 4 * (16384 + 128 * 128 * 2);             // 196608
    const int MAIN64  = 4 * (16384 + 64 * 128 * 2);              // 131072
    const int EPI1 = 128 * 66 * 4 + 128 * 128 * 4;               // 99328
    const int EPI2 = 128 * 66 * 4 + 128 * 64 * 4;                // 66560
    const int RB128 = 8 * 32 * 33 * 4;                           // 33792
    const int RB64  = 8 * 32 * 17 * 4;                           // 17408
    const int SM_L1 = ((MAIN128 > EPI1) ? MAIN128 : EPI1) + RB128;  // 230400
    const int SM_L2 = ((MAIN128 > EPI2) ? MAIN128 : EPI2) + RB128;  // 230400
    const int SM_L3 = MAIN64 + RB64;                                // 148480
    cudaFuncSetAttribute(spmm_hmma<128, 128, 0, true>,
                         cudaFuncAttributeMaxDynamicSharedMemorySize, SM_L1);
    cudaFuncSetAttribute(spmm_hmma<128, 64, 1, true>,
                         cudaFuncAttributeMaxDynamicSharedMemorySize, SM_L2);
    cudaFuncSetAttribute(spmm_hmma<64, 0, 0, false>,
                         cudaFuncAttributeMaxDynamicSharedMemorySize, SM_L3);

    convert_rowsum<<<GN, 256>>>(adj);

    // layer 0 feat: Zs1 = dinv ⊙ (x@W0)  -> buffer 0
    feat_gemm<64, 128><<<GN / 64, 256>>>(x, W0);

    // layer 1: h1 = relu(An@Zs1 + b0); fused: Zs2 = dinv ⊙ (h1@W1) -> buffer 1
    spmm_hmma<128, 128, 0, true><<<GN / 64, 512, SM_L1>>>(b0, W1, nullptr);

    // layer 2: h2 = relu(An@Zs2 + b1); fused: Zs3 = dinv ⊙ (h2@W2) -> buffer 0
    spmm_hmma<128, 64, 1, true><<<GN / 64, 512, SM_L2>>>(b1, W2, nullptr);

    // layer 3: out = An@Zs3 + b2
    spmm_hmma<64, 0, 0, false><<<GN / 64, 512, SM_L3>>>(b2, nullptr, out);
}